// round 14
// baseline (speedup 1.0000x reference)
#include <cuda_runtime.h>
#include <cuda_fp16.h>
#include <math.h>
#include <cstdint>

#define HP 138
#define WP 138
#define NB 8
#define ND 200
#define NK 32
#define H0 550
#define W0 550
#define NC 3
#define GSTRIDE 144            // padded gaussian row

#define NPAIR  151250          // 550*550/2
#define NPREP  1600            // one block per (b,n)
#define NASM   1296            // 9 wx * 18 hy * 8 b
#define NFINB  591             // ceil(NPAIR/256)
#define NGRID  (NPREP + NASM + NFINB)

typedef unsigned long long u64;
typedef unsigned int u32;

// ---------------- packed f32x2 helpers --------------------------------------
__device__ __forceinline__ u64 pack2(float lo, float hi) {
    u64 r; asm("mov.b64 %0, {%1, %2};" : "=l"(r) : "f"(lo), "f"(hi)); return r;
}
__device__ __forceinline__ void unpack2(u64 v, float& lo, float& hi) {
    asm("mov.b64 {%0, %1}, %2;" : "=f"(lo), "=f"(hi) : "l"(v));
}
__device__ __forceinline__ u64 fma2_(u64 a, u64 b, u64 c) {
    u64 d; asm("fma.rn.f32x2 %0, %1, %2, %3;" : "=l"(d) : "l"(a), "l"(b), "l"(c)); return d;
}
__device__ __forceinline__ u64 add2_(u64 a, u64 b) {
    u64 d; asm("add.rn.f32x2 %0, %1, %2;" : "=l"(d) : "l"(a), "l"(b)); return d;
}
__device__ __forceinline__ u64 mul2_(u64 a, u64 b) {
    u64 d; asm("mul.rn.f32x2 %0, %1, %2;" : "=l"(d) : "l"(a), "l"(b)); return d;
}
__device__ __forceinline__ float tanh_(float x) {
    float y; asm("tanh.approx.f32 %0, %1;" : "=f"(y) : "f"(x)); return y;
}
__device__ __forceinline__ u32 packh2(float lo, float hi) {
    u32 r; asm("cvt.rn.f16x2.f32 %0, %1, %2;" : "=r"(r) : "f"(hi), "f"(lo)); return r;
}

// ---------------- mma / ldmatrix wrappers (plain sm_80+ PTX) ----------------
__device__ __forceinline__ u32 smem_u32(const void* p) {
    u32 a; asm("{ .reg .u64 t; cvta.to.shared.u64 t, %1; cvt.u32.u64 %0, t; }"
               : "=r"(a) : "l"(p));
    return a;
}
__device__ __forceinline__ void ldm_x4(u32* r, u32 addr) {
    asm volatile("ldmatrix.sync.aligned.m8n8.x4.shared.b16 {%0,%1,%2,%3}, [%4];"
        : "=r"(r[0]), "=r"(r[1]), "=r"(r[2]), "=r"(r[3]) : "r"(addr));
}
__device__ __forceinline__ void ldm_x2(u32* r, u32 addr) {
    asm volatile("ldmatrix.sync.aligned.m8n8.x2.shared.b16 {%0,%1}, [%2];"
        : "=r"(r[0]), "=r"(r[1]) : "r"(addr));
}
__device__ __forceinline__ void mma_f16(float* c, const u32* a, const u32* b) {
    asm volatile(
        "mma.sync.aligned.m16n8k16.row.col.f32.f16.f16.f32 "
        "{%0,%1,%2,%3}, {%4,%5,%6,%7}, {%8,%9}, {%0,%1,%2,%3};"
        : "+f"(c[0]), "+f"(c[1]), "+f"(c[2]), "+f"(c[3])
        : "r"(a[0]), "r"(a[1]), "r"(a[2]), "r"(a[3]), "r"(b[0]), "r"(b[1]));
}

// ---------------- scratch (device globals; zero-initialized) ----------------
__device__ float g_fc [NB * HP * WP];
__device__ float g_partial[2048];
__device__ unsigned int g_count;
__device__ unsigned int g_prep_flag[NB];     // ==200 when batch b prepped
__device__ unsigned int g_asm_hy[18];        // ==72 when row-band hy done
__device__ unsigned char g_maskh[NB][ND * 80];
__device__ float g_gxT[NB * ND * GSTRIDE];
__device__ float g_gyT[NB * ND * GSTRIDE];

// ---------------- SMEM layout (assemble role; bytes) ------------------------
#define SM_B   0                       // mask fp16  [200][80B] = 16000
#define SM_P   16000                   // proto fp16 [128][80B] = 10240
#define SM_GX  26240                   // gx f32     [200][20]  = 16000
#define SM_GY  42240                   // gy f32     [200][12]  = 9600
#define SM_TOTAL 51840

// ---------------- ONE fused kernel: prep | assemble | finalize --------------
// CTAs dispatch in ascending bid; consumers are placed after their producers,
// so flag spin-waits cannot deadlock. Flags are reset by the is_last block at
// the end of every launch (deterministic across graph replays).
__global__ __launch_bounds__(256, 3)
void fused_kernel(const float* __restrict__ proto,
                  const float* __restrict__ maskp,
                  const float* __restrict__ loc,
                  const float* __restrict__ confp,
                  const float* __restrict__ orig,
                  float* __restrict__ out) {
    extern __shared__ char smem[];
    int bid = blockIdx.x;
    int tid = threadIdx.x;
    const float scale = (float)HP / (float)H0;

    // ================= role 0: prep (one (b,n) per block) ===================
    if (bid < NPREP) {
        int bn = bid;
        int b  = bn / ND;
        int n  = bn - b * ND;
        float4 l = ((const float4*)loc)[bn];

        if (tid < 32) {
            float v = 0.5f * maskp[(size_t)bn * NK + tid];  // 0.5: tanh sigmoid
            __half h = __float2half_rn(v);
            *(unsigned short*)&g_maskh[b][n * 80 + 2 * tid] = *(unsigned short*)&h;
        }
        if (tid < GSTRIDE) {
            float gx = 0.0f, gy = 0.0f;
            if (tid < WP) {
                float xs = (tid + 0.5f) * (1.0f / (float)WP);
                float s  = fmaxf(l.z, 1e-3f);
                float iv = __fdividef(0.5f, s * s);
                float d  = xs - l.x;
                gx = __expf(-d * d * iv);

                float ys = (tid + 0.5f) * (1.0f / (float)HP);
                float sh = fmaxf(l.w, 1e-3f);
                float ih = __fdividef(0.5f, sh * sh);
                float dh = ys - l.y;
                gy = __expf(-dh * dh * ih) * confp[bn];
            }
            g_gxT[(size_t)bn * GSTRIDE + tid] = gx;
            g_gyT[(size_t)bn * GSTRIDE + tid] = gy;
        }
        __syncthreads();
        if (tid == 0) { __threadfence(); atomicAdd(&g_prep_flag[b], 1u); }
        return;
    }

    // ================= role 1: assemble (HMMA + sigmoid + moments) ==========
    if (bid < NPREP + NASM) {
        u32 sbase = smem_u32(smem);
        int idx = bid - NPREP;
        int wx = idx % 9;
        int t2 = idx / 9;
        int b  = t2 & 7;           // b fast, hy slow -> row-bands finish in order
        int hy = t2 >> 3;
        int w0 = wx * 16, h0 = hy * 8;
        int wid  = tid >> 5;
        int lane = tid & 31;

        // proto staging first (independent of prep) — overlaps the spin
        if (tid < 128) {
            int r  = tid;
            int hh = min(h0 + (r >> 4), HP - 1);
            int ww = min(w0 + (r & 15), WP - 1);
            const float4* ps = (const float4*)(proto +
                ((size_t)(b * HP + hh) * WP + ww) * NK);
            #pragma unroll
            for (int c = 0; c < 4; c++) {
                float4 q0 = ps[2 * c + 0];
                float4 q1 = ps[2 * c + 1];
                uint4 o;
                o.x = packh2(q0.x, q0.y);
                o.y = packh2(q0.z, q0.w);
                o.z = packh2(q1.x, q1.y);
                o.w = packh2(q1.z, q1.w);
                *(uint4*)(smem + SM_P + r * 80 + c * 16) = o;
            }
        }
        // wait for this batch's prep
        if (tid == 0) {
            volatile unsigned int* f = &g_prep_flag[b];
            while (*f != (unsigned)ND) {}
            __threadfence();
        }
        __syncthreads();

        if (tid >= 128) {
            int t = tid - 128;
            const float4* src = (const float4*)g_maskh[b];
            for (int j = t; j < 1000; j += 128)
                *(float4*)(smem + SM_B + j * 16) = src[j];
        }
        {
            const float* gxg = g_gxT + (size_t)b * ND * GSTRIDE + w0;
            const float* gyg = g_gyT + (size_t)b * ND * GSTRIDE + h0;
            for (int i = tid; i < ND * 4; i += 256) {
                int n = i >> 2, j = i & 3;
                float4 v = *(const float4*)(gxg + n * GSTRIDE + 4 * j);
                *(float4*)(smem + SM_GX + (n * 20 + 4 * j) * 4) = v;
            }
            for (int i = tid; i < ND * 2; i += 256) {
                int n = i >> 1, j = i & 1;
                float4 v = *(const float4*)(gyg + n * GSTRIDE + 4 * j);
                *(float4*)(smem + SM_GY + (n * 12 + 4 * j) * 4) = v;
            }
        }
        __syncthreads();

        u32 a_row_off = (u32)((wid * 16 + (lane & 15)) * 80 + ((lane & 16)));
        u32 a0[4], a1[4];
        ldm_x4(a0, sbase + SM_P + a_row_off);
        ldm_x4(a1, sbase + SM_P + a_row_off + 32);

        u32 b_base = sbase + SM_B + (u32)((lane & 7) * 80 + ((lane & 8) << 1));

        const float* gx_s = (const float*)(smem + SM_GX);
        const float* gy_s = (const float*)(smem + SM_GY);
        int g  = lane >> 2;
        int ca = (lane & 3) * 2;
        const u64 HALF2 = pack2(0.5f, 0.5f);

        u64 s1r0 = 0, s2r0 = 0, s1r1 = 0, s2r1 = 0;

        u32 bb[2][4];
        ldm_x2(bb[0] + 0, b_base + 0);
        ldm_x2(bb[0] + 2, b_base + 32);

        #pragma unroll 2
        for (int nt = 0; nt < 25; nt++) {
            const u32* bc = bb[nt & 1];
            u32*       bn = bb[(nt & 1) ^ 1];
            if (nt < 24) {
                u32 brow = (u32)((nt + 1) * 8 * 80);
                ldm_x2(bn + 0, b_base + brow);
                ldm_x2(bn + 2, b_base + brow + 32);
            }

            float c[4] = {0.f, 0.f, 0.f, 0.f};
            mma_f16(c, a0, bc + 0);
            mma_f16(c, a1, bc + 2);

            int na = nt * 8 + ca, nb_ = na + 1;
            float gya = gy_s[na * 12 + wid];
            float gyb = gy_s[nb_ * 12 + wid];
            float ga0 = gx_s[na * 20 + g]      * gya;
            float gb0 = gx_s[nb_ * 20 + g]     * gyb;
            float ga1 = gx_s[na * 20 + 8 + g]  * gya;
            float gb1 = gx_s[nb_ * 20 + 8 + g] * gyb;

            u64 t0 = pack2(tanh_(c[0]), tanh_(c[1]));
            u64 t1 = pack2(tanh_(c[2]), tanh_(c[3]));
            u64 sg0 = fma2_(t0, HALF2, HALF2);
            u64 sg1 = fma2_(t1, HALF2, HALF2);
            u64 mc0 = mul2_(sg0, pack2(ga0, gb0));
            u64 mc1 = mul2_(sg1, pack2(ga1, gb1));
            s1r0 = add2_(s1r0, mc0);
            s2r0 = fma2_(mc0, mc0, s2r0);
            s1r1 = add2_(s1r1, mc1);
            s2r1 = fma2_(mc1, mc1, s2r1);
        }

        float x, y;
        unpack2(s1r0, x, y); float s10 = x + y;
        unpack2(s2r0, x, y); float s20 = x + y;
        unpack2(s1r1, x, y); float s11 = x + y;
        unpack2(s2r1, x, y); float s21 = x + y;

        #pragma unroll
        for (int m = 1; m <= 2; m <<= 1) {
            s10 += __shfl_xor_sync(0xFFFFFFFFu, s10, m);
            s20 += __shfl_xor_sync(0xFFFFFFFFu, s20, m);
            s11 += __shfl_xor_sync(0xFFFFFFFFu, s11, m);
            s21 += __shfl_xor_sync(0xFFFFFFFFu, s21, m);
        }

        if ((lane & 3) == 0) {
            int h = h0 + wid;
            if (h < HP) {
                float* dst = g_fc + (size_t)(b * HP + h) * WP;
                int wa = w0 + g;
                if (wa < WP) {
                    float fc = 1.0f - __fdividef(s20, s10 + 1e-6f);
                    if (isnan(fc)) fc = 0.0f;
                    dst[wa] = fc;
                }
                int wb = w0 + 8 + g;
                if (wb < WP) {
                    float fc = 1.0f - __fdividef(s21, s11 + 1e-6f);
                    if (isnan(fc)) fc = 0.0f;
                    dst[wb] = fc;
                }
            }
        }
        __syncthreads();
        if (tid == 0) { __threadfence(); atomicAdd(&g_asm_hy[hy], 1u); }
        return;
    }

    // ================= role 2: finalize (2 px/thread, streams behind) =======
    {
        float* red = (float*)smem;                  // 256 floats
        __shared__ bool is_last;
        int cq = bid - (NPREP + NASM);

        // row-band dependency range for this block
        int q_first = cq * 256;
        int q_last  = min(q_first + 255, NPAIR - 1);
        int i_f = (2 * q_first) / W0;
        int i_l = (2 * q_last + 1) / W0;
        int ylo = max((int)floorf((i_f + 0.5f) * scale - 0.5f), 0);
        int yhi = min((int)floorf((i_l + 0.5f) * scale - 0.5f) + 1, HP - 1);
        if (tid == 0) {
            for (int h = (ylo >> 3); h <= (yhi >> 3); h++) {
                volatile unsigned int* f = &g_asm_hy[h];
                while (*f != 72u) {}
            }
            __threadfence();
        }
        __syncthreads();

        int q = q_first + tid;
        float val = 0.0f;
        if (q < NPAIR) {
            int p0 = 2 * q;
            int i = p0 / W0, j = p0 - i * W0;

            float sy = (i + 0.5f) * scale - 0.5f;
            float fy0 = floorf(sy);
            float fy = sy - fy0;
            int y0 = (int)fy0;
            int y0c = min(max(y0, 0), HP - 1);
            int y1c = min(max(y0 + 1, 0), HP - 1);

            float fxs[2];
            int x0c[2], x1c[2];
            #pragma unroll
            for (int px = 0; px < 2; px++) {
                float sx = (j + px + 0.5f) * scale - 0.5f;
                float fx0 = floorf(sx);
                fxs[px] = sx - fx0;
                int x0 = (int)fx0;
                x0c[px] = min(max(x0, 0), WP - 1);
                x1c[px] = min(max(x0 + 1, 0), WP - 1);
            }

            float r[2][NB];
            float tot0 = 0.f, tot1 = 0.f;
            #pragma unroll
            for (int b = 0; b < NB; b++) {
                const float* f0 = g_fc + (size_t)b * HP * WP + y0c * WP;
                const float* f1 = g_fc + (size_t)b * HP * WP + y1c * WP;
                #pragma unroll
                for (int px = 0; px < 2; px++) {
                    float v00 = __ldg(f0 + x0c[px]);
                    float v01 = __ldg(f0 + x1c[px]);
                    float v10 = __ldg(f1 + x0c[px]);
                    float v11 = __ldg(f1 + x1c[px]);
                    float v0 = v00 + (v01 - v00) * fxs[px];
                    float v1 = v10 + (v11 - v10) * fxs[px];
                    float rv = v0 + (v1 - v0) * fy;
                    r[px][b] = rv;
                    if (px == 0) tot0 += rv; else tot1 += rv;
                }
            }
            float it0  = __fdividef(1.0f, tot0);
            float ite0 = __fdividef(1.0f, tot0 + 1e-6f);
            float it1  = __fdividef(1.0f, tot1);
            float ite1 = __fdividef(1.0f, tot1 + 1e-6f);

            #pragma unroll
            for (int c = 0; c < NC; c++) {
                float2 ov[NB];
                #pragma unroll
                for (int b = 0; b < NB; b++)
                    ov[b] = __ldg((const float2*)(orig +
                             ((size_t)(b * NC + c)) * (H0 * W0) + p0));
                float s0 = 0.f, s1 = 0.f;
                #pragma unroll
                for (int b = 0; b < NB; b++) {
                    s0 = fmaf(ov[b].x, r[0][b], s0);
                    s1 = fmaf(ov[b].y, r[1][b], s1);
                }
                float wm0 = s0 * it0, wm1 = s1 * it1;
                float a0 = 0.f, a1 = 0.f;
                #pragma unroll
                for (int b = 0; b < NB; b++) {
                    float d0 = ov[b].x - wm0;
                    float d1 = ov[b].y - wm1;
                    a0 = fmaf(d0 * d0, r[0][b], a0);
                    a1 = fmaf(d1 * d1, r[1][b], a1);
                }
                val += a0 * ite0 + a1 * ite1;
            }
            val *= (float)NB / (float)NK;
        }

        red[tid] = val;
        __syncthreads();
        #pragma unroll
        for (int s = 128; s > 0; s >>= 1) {
            if (tid < s) red[tid] += red[tid + s];
            __syncthreads();
        }

        if (tid == 0) {
            g_partial[cq] = red[0];
            __threadfence();
            unsigned int prev = atomicInc(&g_count, NFINB - 1);
            is_last = (prev == NFINB - 1);
        }
        __syncthreads();

        if (is_last) {
            __threadfence();
            float s = 0.0f;
            for (int k = tid; k < NFINB; k += 256) s += g_partial[k];
            red[tid] = s;
            __syncthreads();
            #pragma unroll
            for (int st = 128; st > 0; st >>= 1) {
                if (tid < st) red[tid] += red[tid + st];
                __syncthreads();
            }
            // reset dataflow flags for the next graph replay
            if (tid < NB) g_prep_flag[tid] = 0u;
            if (tid < 18) g_asm_hy[tid] = 0u;
            if (tid == 0) out[0] = red[0];
        }
    }
}

// ---------------- launch ------------------------------------------------------
extern "C" void kernel_launch(void* const* d_in, const int* in_sizes, int n_in,
                              void* d_out, int out_size) {
    const float* original = (const float*)d_in[0];  // [8,3,550,550]
    const float* loc      = (const float*)d_in[1];  // [8,200,4]
    const float* maskp    = (const float*)d_in[2];  // [8,200,32]
    const float* confp    = (const float*)d_in[3];  // [8,200]
    const float* proto    = (const float*)d_in[4];  // [8,138,138,32]
    float* out = (float*)d_out;

    static bool attr_set = false;
    if (!attr_set) {
        cudaFuncSetAttribute(fused_kernel,
                             cudaFuncAttributeMaxDynamicSharedMemorySize,
                             SM_TOTAL);
        attr_set = true;
    }

    fused_kernel<<<NGRID, 256, SM_TOTAL>>>(proto, maskp, loc, confp,
                                           original, out);
}

// round 15
// speedup vs baseline: 1.2243x; 1.2243x over previous
#include <cuda_runtime.h>
#include <cuda_fp16.h>
#include <math.h>
#include <cstdint>

#define HP 138
#define WP 138
#define NB 8
#define ND 200
#define NK 32
#define H0 550
#define W0 550
#define NC 3
#define NBLK_FIN 296           // 75625 quad-pixels / 256, rounded up
#define NQUAD 75625            // 550*550/4
#define GSTRIDE 144            // padded gaussian row

typedef unsigned long long u64;
typedef unsigned int u32;

// ---------------- packed f32x2 helpers --------------------------------------
__device__ __forceinline__ u64 pack2(float lo, float hi) {
    u64 r; asm("mov.b64 %0, {%1, %2};" : "=l"(r) : "f"(lo), "f"(hi)); return r;
}
__device__ __forceinline__ void unpack2(u64 v, float& lo, float& hi) {
    asm("mov.b64 {%0, %1}, %2;" : "=f"(lo), "=f"(hi) : "l"(v));
}
__device__ __forceinline__ u64 fma2_(u64 a, u64 b, u64 c) {
    u64 d; asm("fma.rn.f32x2 %0, %1, %2, %3;" : "=l"(d) : "l"(a), "l"(b), "l"(c)); return d;
}
__device__ __forceinline__ u64 add2_(u64 a, u64 b) {
    u64 d; asm("add.rn.f32x2 %0, %1, %2;" : "=l"(d) : "l"(a), "l"(b)); return d;
}
__device__ __forceinline__ u64 mul2_(u64 a, u64 b) {
    u64 d; asm("mul.rn.f32x2 %0, %1, %2;" : "=l"(d) : "l"(a), "l"(b)); return d;
}
__device__ __forceinline__ float tanh_(float x) {
    float y; asm("tanh.approx.f32 %0, %1;" : "=f"(y) : "f"(x)); return y;
}
// pack two f32 -> f16x2 (first arg -> low half)
__device__ __forceinline__ u32 packh2(float lo, float hi) {
    u32 r; asm("cvt.rn.f16x2.f32 %0, %1, %2;" : "=r"(r) : "f"(hi), "f"(lo)); return r;
}

// ---------------- mma / ldmatrix wrappers (plain sm_80+ PTX) ----------------
__device__ __forceinline__ u32 smem_u32(const void* p) {
    u32 a; asm("{ .reg .u64 t; cvta.to.shared.u64 t, %1; cvt.u32.u64 %0, t; }"
               : "=r"(a) : "l"(p));
    return a;
}
__device__ __forceinline__ void ldm_x4(u32* r, u32 addr) {
    asm volatile("ldmatrix.sync.aligned.m8n8.x4.shared.b16 {%0,%1,%2,%3}, [%4];"
        : "=r"(r[0]), "=r"(r[1]), "=r"(r[2]), "=r"(r[3]) : "r"(addr));
}
__device__ __forceinline__ void ldm_x2(u32* r, u32 addr) {
    asm volatile("ldmatrix.sync.aligned.m8n8.x2.shared.b16 {%0,%1}, [%2];"
        : "=r"(r[0]), "=r"(r[1]) : "r"(addr));
}
__device__ __forceinline__ void mma_f16(float* c, const u32* a, const u32* b) {
    asm volatile(
        "mma.sync.aligned.m16n8k16.row.col.f32.f16.f16.f32 "
        "{%0,%1,%2,%3}, {%4,%5,%6,%7}, {%8,%9}, {%0,%1,%2,%3};"
        : "+f"(c[0]), "+f"(c[1]), "+f"(c[2]), "+f"(c[3])
        : "r"(a[0]), "r"(a[1]), "r"(a[2]), "r"(a[3]), "r"(b[0]), "r"(b[1]));
}

// ---------------- scratch (device globals; no allocations allowed) ----------
__device__ float g_fc [NB * HP * WP];      // final_conf  [b,h,w]
__device__ float g_partial[2048];
__device__ unsigned int g_count;
__device__ unsigned char g_maskh[NB][ND * 80];   // fp16 mask, 0.5-prescaled
__device__ float g_gxT[NB * ND * GSTRIDE];       // gx         [b,n,w]
__device__ float g_gyT[NB * ND * GSTRIDE];       // gy * conf  [b,n,h]

// ---------------- SMEM layout for assemble (bytes) --------------------------
#define SM_B   0                       // mask fp16  [200][80B] = 16000
#define SM_P   16000                   // proto fp16 [128][80B] = 10240
#define SM_GX  26240                   // gx f32     [200][20]  = 16000
#define SM_GY  42240                   // gy f32     [200][12]  = 9600
#define SM_TOTAL 51840

// ---------------- Kernel 0: prep — fp16 mask + gaussian tables --------------
// One block per (b, n): 160 threads. The per-(b,n) constants (1/(2 sx^2),
// 1/(2 sy^2), conf) are computed ONCE by thread 0 and broadcast through smem,
// halving the per-thread MUFU count (prep is MUFU-rate-bound).
__global__ __launch_bounds__(160)
void prep_kernel(const float* __restrict__ mask,
                 const float* __restrict__ loc,
                 const float* __restrict__ conf) {
    __shared__ float sc[4];            // ivx, ivy, conf, (pad)
    int bn = blockIdx.x;               // b*ND + n
    int b  = bn / ND;
    int n  = bn - b * ND;
    int t  = threadIdx.x;

    float4 l = ((const float4*)loc)[bn];

    if (t == 0) {
        float sx = fmaxf(l.z, 1e-3f);
        float sy = fmaxf(l.w, 1e-3f);
        sc[0] = __fdividef(0.5f, sx * sx);
        sc[1] = __fdividef(0.5f, sy * sy);
        sc[2] = conf[bn];
    }

    if (t < 32) {
        float v = 0.5f * mask[(size_t)bn * NK + t];   // 0.5 for tanh sigmoid
        __half h = __float2half_rn(v);
        *(unsigned short*)&g_maskh[b][n * 80 + 2 * t] = *(unsigned short*)&h;
    }
    __syncthreads();

    if (t < GSTRIDE) {
        float gx = 0.0f, gy = 0.0f;
        if (t < WP) {
            float xs = (t + 0.5f) * (1.0f / (float)WP);
            float d  = xs - l.x;
            gx = __expf(-d * d * sc[0]);

            float ys = (t + 0.5f) * (1.0f / (float)HP);
            float dh = ys - l.y;
            gy = __expf(-dh * dh * sc[1]) * sc[2];
        }
        g_gxT[(size_t)bn * GSTRIDE + t] = gx;
        g_gyT[(size_t)bn * GSTRIDE + t] = gy;
    }
}

// ---------------- Kernel 1: HMMA assemble + tanh sigmoid + moments ----------
// (byte-identical to the 38.5us R9 version)
__global__ __launch_bounds__(256, 3)
void assemble_kernel(const float* __restrict__ proto) {
    extern __shared__ char smem[];
    u32 sbase = smem_u32(smem);
    int tid  = threadIdx.x;
    int wid  = tid >> 5;
    int lane = tid & 31;
    int b   = blockIdx.z;
    int w0  = blockIdx.x * 16;
    int h0  = blockIdx.y * 8;

    // ---- staging ----
    if (tid < 128) {
        int r  = tid;
        int hh = min(h0 + (r >> 4), HP - 1);
        int ww = min(w0 + (r & 15), WP - 1);
        const float4* ps = (const float4*)(proto +
            ((size_t)(b * HP + hh) * WP + ww) * NK);
        #pragma unroll
        for (int c = 0; c < 4; c++) {
            float4 q0 = ps[2 * c + 0];
            float4 q1 = ps[2 * c + 1];
            uint4 o;
            o.x = packh2(q0.x, q0.y);
            o.y = packh2(q0.z, q0.w);
            o.z = packh2(q1.x, q1.y);
            o.w = packh2(q1.z, q1.w);
            *(uint4*)(smem + SM_P + r * 80 + c * 16) = o;
        }
    } else {
        int t = tid - 128;
        const float4* src = (const float4*)g_maskh[b];
        for (int j = t; j < 1000; j += 128)
            *(float4*)(smem + SM_B + j * 16) = src[j];
    }
    {
        const float* gxg = g_gxT + (size_t)b * ND * GSTRIDE + w0;
        const float* gyg = g_gyT + (size_t)b * ND * GSTRIDE + h0;
        for (int i = tid; i < ND * 4; i += 256) {       // gx: [n][20] stride
            int n = i >> 2, j = i & 3;
            float4 v = *(const float4*)(gxg + n * GSTRIDE + 4 * j);
            *(float4*)(smem + SM_GX + (n * 20 + 4 * j) * 4) = v;
        }
        for (int i = tid; i < ND * 2; i += 256) {       // gy: [n][12] stride
            int n = i >> 1, j = i & 1;
            float4 v = *(const float4*)(gyg + n * GSTRIDE + 4 * j);
            *(float4*)(smem + SM_GY + (n * 12 + 4 * j) * 4) = v;
        }
    }
    __syncthreads();

    // ---- A fragments (proto fp16, 16x32), loaded once ----
    u32 a_row_off = (u32)((wid * 16 + (lane & 15)) * 80 + ((lane & 16)));
    u32 a0[4], a1[4];
    ldm_x4(a0, sbase + SM_P + a_row_off);        // k0-15
    ldm_x4(a1, sbase + SM_P + a_row_off + 32);   // k16-31

    u32 b_base = sbase + SM_B + (u32)((lane & 7) * 80 + ((lane & 8) << 1));

    const float* gx_s = (const float*)(smem + SM_GX);
    const float* gy_s = (const float*)(smem + SM_GY);
    int g  = lane >> 2;
    int ca = (lane & 3) * 2;
    const u64 HALF2 = pack2(0.5f, 0.5f);

    u64 s1r0 = 0, s2r0 = 0, s1r1 = 0, s2r1 = 0;

    u32 bb[2][4];
    ldm_x2(bb[0] + 0, b_base + 0);
    ldm_x2(bb[0] + 2, b_base + 32);

    #pragma unroll 2
    for (int nt = 0; nt < 25; nt++) {
        const u32* bc = bb[nt & 1];
        u32*       bn = bb[(nt & 1) ^ 1];
        if (nt < 24) {
            u32 brow = (u32)((nt + 1) * 8 * 80);
            ldm_x2(bn + 0, b_base + brow);
            ldm_x2(bn + 2, b_base + brow + 32);
        }

        float c[4] = {0.f, 0.f, 0.f, 0.f};
        mma_f16(c, a0, bc + 0);
        mma_f16(c, a1, bc + 2);

        int na = nt * 8 + ca, nb_ = na + 1;
        float gya = gy_s[na * 12 + wid];
        float gyb = gy_s[nb_ * 12 + wid];
        float ga0 = gx_s[na * 20 + g]      * gya;
        float gb0 = gx_s[nb_ * 20 + g]     * gyb;
        float ga1 = gx_s[na * 20 + 8 + g]  * gya;
        float gb1 = gx_s[nb_ * 20 + 8 + g] * gyb;

        u64 t0 = pack2(tanh_(c[0]), tanh_(c[1]));
        u64 t1 = pack2(tanh_(c[2]), tanh_(c[3]));
        u64 sg0 = fma2_(t0, HALF2, HALF2);
        u64 sg1 = fma2_(t1, HALF2, HALF2);
        u64 mc0 = mul2_(sg0, pack2(ga0, gb0));
        u64 mc1 = mul2_(sg1, pack2(ga1, gb1));
        s1r0 = add2_(s1r0, mc0);
        s2r0 = fma2_(mc0, mc0, s2r0);
        s1r1 = add2_(s1r1, mc1);
        s2r1 = fma2_(mc1, mc1, s2r1);
    }

    float x, y;
    unpack2(s1r0, x, y); float s10 = x + y;
    unpack2(s2r0, x, y); float s20 = x + y;
    unpack2(s1r1, x, y); float s11 = x + y;
    unpack2(s2r1, x, y); float s21 = x + y;

    #pragma unroll
    for (int m = 1; m <= 2; m <<= 1) {
        s10 += __shfl_xor_sync(0xFFFFFFFFu, s10, m);
        s20 += __shfl_xor_sync(0xFFFFFFFFu, s20, m);
        s11 += __shfl_xor_sync(0xFFFFFFFFu, s11, m);
        s21 += __shfl_xor_sync(0xFFFFFFFFu, s21, m);
    }

    if ((lane & 3) == 0) {
        int h = h0 + wid;
        if (h < HP) {
            float* dst = g_fc + (size_t)(b * HP + h) * WP;
            int wa = w0 + g;
            if (wa < WP) {
                float fc = 1.0f - __fdividef(s20, s10 + 1e-6f);
                if (isnan(fc)) fc = 0.0f;
                dst[wa] = fc;
            }
            int wb = w0 + 8 + g;
            if (wb < WP) {
                float fc = 1.0f - __fdividef(s21, s11 + 1e-6f);
                if (isnan(fc)) fc = 0.0f;
                dst[wb] = fc;
            }
        }
    }
}

// ---------------- Kernel C: bilinear 138->550, weighted variance, reduce ----
// (byte-identical to the 38.5us R9 version)
__global__ __launch_bounds__(256)
void finalize_kernel(const float* __restrict__ orig, float* __restrict__ out) {
    int q = blockIdx.x * 256 + threadIdx.x;
    float val = 0.0f;
    if (q < NQUAD) {
        int p0 = 4 * q;

        float fys[4], fxs[4];
        int y0c[4], y1c[4], x0c[4], x1c[4];
        #pragma unroll
        for (int px = 0; px < 4; px++) {
            int p = p0 + px;
            int i = p / W0, j = p - i * W0;
            const float scale = (float)HP / (float)H0;
            float sy = (i + 0.5f) * scale - 0.5f;
            float sx = (j + 0.5f) * scale - 0.5f;
            float fy0 = floorf(sy), fx0 = floorf(sx);
            fys[px] = sy - fy0; fxs[px] = sx - fx0;
            int y0 = (int)fy0, x0 = (int)fx0;
            y0c[px] = min(max(y0, 0), HP - 1);
            y1c[px] = min(max(y0 + 1, 0), HP - 1);
            x0c[px] = min(max(x0, 0), WP - 1);
            x1c[px] = min(max(x0 + 1, 0), WP - 1);
        }

        float r[4][NB];
        float tot[4] = {0.f, 0.f, 0.f, 0.f};
        #pragma unroll
        for (int b = 0; b < NB; b++) {
            const float* f = g_fc + (size_t)b * HP * WP;
            #pragma unroll
            for (int px = 0; px < 4; px++) {
                float v00 = __ldg(f + y0c[px] * WP + x0c[px]);
                float v01 = __ldg(f + y0c[px] * WP + x1c[px]);
                float v10 = __ldg(f + y1c[px] * WP + x0c[px]);
                float v11 = __ldg(f + y1c[px] * WP + x1c[px]);
                float v0 = v00 + (v01 - v00) * fxs[px];
                float v1 = v10 + (v11 - v10) * fxs[px];
                float rv = v0 + (v1 - v0) * fys[px];
                r[px][b] = rv;
                tot[px] += rv;
            }
        }
        float it[4], ite[4];
        #pragma unroll
        for (int px = 0; px < 4; px++) {
            it[px]  = __fdividef(1.0f, tot[px]);
            ite[px] = __fdividef(1.0f, tot[px] + 1e-6f);
        }

        #pragma unroll
        for (int c = 0; c < NC; c++) {
            float4 ov[NB];
            #pragma unroll
            for (int b = 0; b < NB; b++)
                ov[b] = __ldg((const float4*)(orig +
                         ((size_t)(b * NC + c)) * (H0 * W0) + p0));
            #pragma unroll
            for (int px = 0; px < 4; px++) {
                float o[NB];
                #pragma unroll
                for (int b = 0; b < NB; b++) {
                    float4 v = ov[b];
                    o[b] = (px == 0) ? v.x : (px == 1) ? v.y : (px == 2) ? v.z : v.w;
                }
                float s = 0.0f;
                #pragma unroll
                for (int b = 0; b < NB; b++) s = fmaf(o[b], r[px][b], s);
                float wm = s * it[px];
                float acc = 0.0f;
                #pragma unroll
                for (int b = 0; b < NB; b++) {
                    float d = o[b] - wm;
                    acc = fmaf(d * d, r[px][b], acc);
                }
                val += acc * ite[px];
            }
        }
        val *= (float)NB / (float)NK;
    }

    __shared__ float red[256];
    red[threadIdx.x] = val;
    __syncthreads();
    #pragma unroll
    for (int s = 128; s > 0; s >>= 1) {
        if (threadIdx.x < s) red[threadIdx.x] += red[threadIdx.x + s];
        __syncthreads();
    }

    __shared__ bool is_last;
    if (threadIdx.x == 0) {
        g_partial[blockIdx.x] = red[0];
        __threadfence();
        unsigned int prev = atomicInc(&g_count, NBLK_FIN - 1);
        is_last = (prev == NBLK_FIN - 1);
    }
    __syncthreads();

    if (is_last) {
        __threadfence();
        float s = 0.0f;
        for (int i = threadIdx.x; i < NBLK_FIN; i += 256) s += g_partial[i];
        red[threadIdx.x] = s;
        __syncthreads();
        #pragma unroll
        for (int st = 128; st > 0; st >>= 1) {
            if (threadIdx.x < st) red[threadIdx.x] += red[threadIdx.x + st];
            __syncthreads();
        }
        if (threadIdx.x == 0) out[0] = red[0];
    }
}

// ---------------- launch ------------------------------------------------------
extern "C" void kernel_launch(void* const* d_in, const int* in_sizes, int n_in,
                              void* d_out, int out_size) {
    const float* original = (const float*)d_in[0];  // [8,3,550,550]
    const float* loc      = (const float*)d_in[1];  // [8,200,4]
    const float* maskp    = (const float*)d_in[2];  // [8,200,32]
    const float* confp    = (const float*)d_in[3];  // [8,200]
    const float* proto    = (const float*)d_in[4];  // [8,138,138,32]
    float* out = (float*)d_out;

    static bool attr_set = false;
    if (!attr_set) {
        cudaFuncSetAttribute(assemble_kernel,
                             cudaFuncAttributeMaxDynamicSharedMemorySize,
                             SM_TOTAL);
        attr_set = true;
    }

    prep_kernel<<<NB * ND, 160>>>(maskp, loc, confp);

    dim3 gB((WP + 15) / 16, (HP + 7) / 8, NB);   // 9 x 18 x 8 = 1296
    assemble_kernel<<<gB, 256, SM_TOTAL>>>(proto);

    finalize_kernel<<<NBLK_FIN, 256>>>(original, out);
}